// round 1
// baseline (speedup 1.0000x reference)
#include <cuda_runtime.h>
#include <cstdint>

#define IN_CHN  128
#define OUT_CHN 128
#define HW      56
#define PHW     58      // padded 58x58 (1-pixel zero border, valid=0 there)
#define NB      32
#define NW_TOT  (OUT_CHN*IN_CHN*9)
#define SCALE_F 100.0f

// ---- scratch (device globals; no allocation allowed) ----
// packed sign bits (bit=1 means x<0) and validity bits (bit=1 means x!=0)
__device__ uint4 g_abits[NB * PHW * PHW];     // 1.72 MB
__device__ uint4 g_vbits[NB * PHW * PHW];     // 1.72 MB
// packed weight sign bits: layout word index = ((o*9 + tap)*4 + j), bit = channel j*32+lane
__device__ uint4 g_wbits[OUT_CHN * 9];        // 18 KB

// ============================================================
// Kernel 1: weight synthesis + sign bit-pack
// warp wi = ((o*9 + t)*4 + j), lane = channel%32, i = j*32+lane
// ============================================================
__global__ void k_weights(const float* __restrict__ M,
                          const float* __restrict__ Z,
                          const float* __restrict__ rv)
{
    int tid  = blockIdx.x * blockDim.x + threadIdx.x;
    int wi   = tid >> 5;
    int lane = tid & 31;
    if (wi >= OUT_CHN * 9 * 4) return;

    int o = wi / 36;
    int r = wi % 36;
    int t = r >> 2;        // tap 0..8
    int j = r & 3;         // word 0..3
    int i = j * 32 + lane; // input channel

    int idx = (o * IN_CHN + i) * 9 + t;   // flat index into (O,I,3,3)

    float m = M[idx];
    float z[5];
    float s = 0.f;
#pragma unroll
    for (int k = 0; k < 5; k++) { z[k] = Z[k * NW_TOT + idx]; s += z[k] * z[k]; }

    float A   = m * m + s / SCALE_F;
    float inv = rsqrtf(A);
    float w = 0.f;
#pragma unroll
    for (int k = 0; k < 5; k++) w += rv[k] * (z[k] * inv);
    w += m * inv;

    unsigned bits = __ballot_sync(0xFFFFFFFFu, w < 0.f);
    if (lane == 0) ((uint32_t*)g_wbits)[wi] = bits;
}

// ============================================================
// Kernel 2: binarize + bit-pack activations into zero-bordered
// padded array. Thread = one padded pixel; loads are coalesced
// across px (consecutive lanes -> consecutive addresses).
// ============================================================
__global__ void k_pack(const float* __restrict__ x)
{
    int px = threadIdx.x;
    int py = blockIdx.x;
    int b  = blockIdx.y;
    if (px >= PHW) return;

    int pidx = (b * PHW + py) * PHW + px;
    uint32_t aw[4] = {0, 0, 0, 0};
    uint32_t vw[4] = {0, 0, 0, 0};

    if (py >= 1 && py <= HW && px >= 1 && px <= HW) {
        const float* xp = x + (size_t)b * IN_CHN * HW * HW + (py - 1) * HW + (px - 1);
#pragma unroll 8
        for (int c = 0; c < IN_CHN; c++) {
            float val = xp[(size_t)c * HW * HW];
            uint32_t neg = (val < 0.f)  ? 1u : 0u;
            uint32_t nz  = (val != 0.f) ? 1u : 0u;
            aw[c >> 5] |= neg << (c & 31);
            vw[c >> 5] |= nz  << (c & 31);
        }
    }
    g_abits[pidx] = make_uint4(aw[0], aw[1], aw[2], aw[3]);
    g_vbits[pidx] = make_uint4(vw[0], vw[1], vw[2], vw[3]);
}

// ============================================================
// Kernel 3: XNOR-popcount conv.
// CTA = (y, b). 224 threads: strip = tid%28 (2 output x each),
// ogrp = tid/28 (8 groups x 16 output channels each).
// Activations+validity held in registers (3 rows x 4 cols x 4+4
// words); weights streamed per-o from smem (LDS.128 broadcast).
// contrib = sum_valid(1) - 2*popc((a^w)&v); padding handled by
// valid=0 border of the packed array -> zero branches.
// ============================================================
__global__ void __launch_bounds__(224, 2)
k_conv(const float* __restrict__ Alpha, float* __restrict__ out)
{
    __shared__ uint4 wsm[OUT_CHN * 9];
    __shared__ float alsm[OUT_CHN];

    int tid = threadIdx.x;
    int y   = blockIdx.x;   // output row 0..55
    int b   = blockIdx.y;   // batch

    for (int k = tid; k < OUT_CHN * 9; k += 224) wsm[k] = g_wbits[k];
    if (tid < OUT_CHN) alsm[tid] = Alpha[tid];
    __syncthreads();

    int xp = tid % 28;      // strip id
    int og = tid / 28;      // 0..7
    int x0 = xp * 2;        // first output x of strip (padded col base = x0)

    // registers: a[row][col][word], v[row][col][word]
    uint32_t a[3][4][4], v[3][4][4];
    int vsum0 = 0, vsum1 = 0;
#pragma unroll
    for (int r = 0; r < 3; r++) {
#pragma unroll
        for (int c = 0; c < 4; c++) {
            int pidx = (b * PHW + (y + r)) * PHW + (x0 + c);
            uint4 ua = g_abits[pidx];
            uint4 uv = g_vbits[pidx];
            a[r][c][0] = ua.x; a[r][c][1] = ua.y; a[r][c][2] = ua.z; a[r][c][3] = ua.w;
            v[r][c][0] = uv.x; v[r][c][1] = uv.y; v[r][c][2] = uv.z; v[r][c][3] = uv.w;
            int pv = __popc(uv.x) + __popc(uv.y) + __popc(uv.z) + __popc(uv.w);
            if (c < 3) vsum0 += pv;   // pixel0 uses cols 0..2
            if (c > 0) vsum1 += pv;   // pixel1 uses cols 1..3
        }
    }

    float* outp = out + ((size_t)b * OUT_CHN) * (HW * HW) + y * HW + x0;

#pragma unroll 1
    for (int oi = 0; oi < 16; oi++) {
        int o = og * 16 + oi;
        int acc0 = 0, acc1 = 0;
#pragma unroll
        for (int r = 0; r < 3; r++) {
#pragma unroll
            for (int k = 0; k < 3; k++) {
                uint4 w = wsm[o * 9 + r * 3 + k];
                acc0 += __popc((a[r][k][0]     ^ w.x) & v[r][k][0]);
                acc0 += __popc((a[r][k][1]     ^ w.y) & v[r][k][1]);
                acc0 += __popc((a[r][k][2]     ^ w.z) & v[r][k][2]);
                acc0 += __popc((a[r][k][3]     ^ w.w) & v[r][k][3]);
                acc1 += __popc((a[r][k + 1][0] ^ w.x) & v[r][k + 1][0]);
                acc1 += __popc((a[r][k + 1][1] ^ w.y) & v[r][k + 1][1]);
                acc1 += __popc((a[r][k + 1][2] ^ w.z) & v[r][k + 1][2]);
                acc1 += __popc((a[r][k + 1][3] ^ w.w) & v[r][k + 1][3]);
            }
        }
        float al = alsm[o];
        float2 res;
        res.x = al * (float)(vsum0 - 2 * acc0);
        res.y = al * (float)(vsum1 - 2 * acc1);
        *(float2*)(outp + (size_t)o * (HW * HW)) = res;
    }
}

// ============================================================
extern "C" void kernel_launch(void* const* d_in, const int* in_sizes, int n_in,
                              void* d_out, int out_size)
{
    const float* x     = (const float*)d_in[0];  // (32,128,56,56)
    const float* Alpha = (const float*)d_in[1];  // (128,1,1)
    const float* M     = (const float*)d_in[2];  // (128,128,3,3)
    const float* Z     = (const float*)d_in[3];  // (5,128,128,3,3)
    const float* rv    = (const float*)d_in[4];  // (1,5)
    float* out = (float*)d_out;

    // 1) weight synthesis + sign pack: 4608 warps
    k_weights<<<576, 256>>>(M, Z, rv);

    // 2) activation binarize + pack (zero-bordered 58x58)
    k_pack<<<dim3(PHW, NB), 64>>>(x);

    // 3) XNOR-popcount conv + Alpha scale
    k_conv<<<dim3(HW, NB), 224>>>(Alpha, out);
}

// round 2
// speedup vs baseline: 1.0027x; 1.0027x over previous
#include <cuda_runtime.h>
#include <cstdint>

#define IN_CHN  128
#define OUT_CHN 128
#define HW      56
#define PHW     58      // padded 58x58 (1-pixel zero border, valid=0 there)
#define NB      32
#define NW_TOT  (OUT_CHN*IN_CHN*9)
#define SCALE_F 100.0f

// ---- scratch (device globals; no allocation allowed) ----
// packed sign bits (bit=1 means x<0) and validity bits (bit=1 means x!=0)
__device__ uint4 g_abits[NB * PHW * PHW];     // 1.72 MB
__device__ uint4 g_vbits[NB * PHW * PHW];     // 1.72 MB
// packed weight sign bits: layout word index = ((o*9 + tap)*4 + j), bit = channel j*32+lane
__device__ uint4 g_wbits[OUT_CHN * 9];        // 18 KB

// ============================================================
// Kernel 1: weight synthesis + sign bit-pack
// warp wi = ((o*9 + t)*4 + j), lane = channel%32, i = j*32+lane
// ============================================================
__global__ void k_weights(const float* __restrict__ M,
                          const float* __restrict__ Z,
                          const float* __restrict__ rv)
{
    int tid  = blockIdx.x * blockDim.x + threadIdx.x;
    int wi   = tid >> 5;
    int lane = tid & 31;
    if (wi >= OUT_CHN * 9 * 4) return;

    int o = wi / 36;
    int r = wi % 36;
    int t = r >> 2;        // tap 0..8
    int j = r & 3;         // word 0..3
    int i = j * 32 + lane; // input channel

    int idx = (o * IN_CHN + i) * 9 + t;   // flat index into (O,I,3,3)

    float m = M[idx];
    float z[5];
    float s = 0.f;
#pragma unroll
    for (int k = 0; k < 5; k++) { z[k] = Z[k * NW_TOT + idx]; s += z[k] * z[k]; }

    float A   = m * m + s / SCALE_F;
    float inv = rsqrtf(A);
    float w = 0.f;
#pragma unroll
    for (int k = 0; k < 5; k++) w += rv[k] * (z[k] * inv);
    w += m * inv;

    unsigned bits = __ballot_sync(0xFFFFFFFFu, w < 0.f);
    if (lane == 0) ((uint32_t*)g_wbits)[wi] = bits;
}

// ============================================================
// Kernel 2: binarize + bit-pack activations into zero-bordered
// padded array. Thread = one padded pixel; loads are coalesced
// across px (consecutive lanes -> consecutive addresses).
// ============================================================
__global__ void k_pack(const float* __restrict__ x)
{
    int px = threadIdx.x;
    int py = blockIdx.x;
    int b  = blockIdx.y;
    if (px >= PHW) return;

    int pidx = (b * PHW + py) * PHW + px;
    uint32_t aw[4] = {0, 0, 0, 0};
    uint32_t vw[4] = {0, 0, 0, 0};

    if (py >= 1 && py <= HW && px >= 1 && px <= HW) {
        const float* xp = x + (size_t)b * IN_CHN * HW * HW + (py - 1) * HW + (px - 1);
#pragma unroll 8
        for (int c = 0; c < IN_CHN; c++) {
            float val = xp[(size_t)c * HW * HW];
            uint32_t neg = (val < 0.f)  ? 1u : 0u;
            uint32_t nz  = (val != 0.f) ? 1u : 0u;
            aw[c >> 5] |= neg << (c & 31);
            vw[c >> 5] |= nz  << (c & 31);
        }
    }
    g_abits[pidx] = make_uint4(aw[0], aw[1], aw[2], aw[3]);
    g_vbits[pidx] = make_uint4(vw[0], vw[1], vw[2], vw[3]);
}

// ============================================================
// Kernel 3: XNOR-popcount conv.
// CTA = (y, b). 224 threads: strip = tid%28 (2 output x each),
// ogrp = tid/28 (8 groups x 16 output channels each).
// Activations+validity held in registers (3 rows x 4 cols x 4+4
// words); weights streamed per-o from smem (LDS.128 broadcast).
// contrib = sum_valid(1) - 2*popc((a^w)&v); padding handled by
// valid=0 border of the packed array -> zero branches.
// ============================================================
__global__ void __launch_bounds__(224, 2)
k_conv(const float* __restrict__ Alpha, float* __restrict__ out)
{
    __shared__ uint4 wsm[OUT_CHN * 9];
    __shared__ float alsm[OUT_CHN];

    int tid = threadIdx.x;
    int y   = blockIdx.x;   // output row 0..55
    int b   = blockIdx.y;   // batch

    for (int k = tid; k < OUT_CHN * 9; k += 224) wsm[k] = g_wbits[k];
    if (tid < OUT_CHN) alsm[tid] = Alpha[tid];
    __syncthreads();

    int xp = tid % 28;      // strip id
    int og = tid / 28;      // 0..7
    int x0 = xp * 2;        // first output x of strip (padded col base = x0)

    // registers: a[row][col][word], v[row][col][word]
    uint32_t a[3][4][4], v[3][4][4];
    int vsum0 = 0, vsum1 = 0;
#pragma unroll
    for (int r = 0; r < 3; r++) {
#pragma unroll
        for (int c = 0; c < 4; c++) {
            int pidx = (b * PHW + (y + r)) * PHW + (x0 + c);
            uint4 ua = g_abits[pidx];
            uint4 uv = g_vbits[pidx];
            a[r][c][0] = ua.x; a[r][c][1] = ua.y; a[r][c][2] = ua.z; a[r][c][3] = ua.w;
            v[r][c][0] = uv.x; v[r][c][1] = uv.y; v[r][c][2] = uv.z; v[r][c][3] = uv.w;
            int pv = __popc(uv.x) + __popc(uv.y) + __popc(uv.z) + __popc(uv.w);
            if (c < 3) vsum0 += pv;   // pixel0 uses cols 0..2
            if (c > 0) vsum1 += pv;   // pixel1 uses cols 1..3
        }
    }

    float* outp = out + ((size_t)b * OUT_CHN) * (HW * HW) + y * HW + x0;

#pragma unroll 1
    for (int oi = 0; oi < 16; oi++) {
        int o = og * 16 + oi;
        int acc0 = 0, acc1 = 0;
#pragma unroll
        for (int r = 0; r < 3; r++) {
#pragma unroll
            for (int k = 0; k < 3; k++) {
                uint4 w = wsm[o * 9 + r * 3 + k];
                acc0 += __popc((a[r][k][0]     ^ w.x) & v[r][k][0]);
                acc0 += __popc((a[r][k][1]     ^ w.y) & v[r][k][1]);
                acc0 += __popc((a[r][k][2]     ^ w.z) & v[r][k][2]);
                acc0 += __popc((a[r][k][3]     ^ w.w) & v[r][k][3]);
                acc1 += __popc((a[r][k + 1][0] ^ w.x) & v[r][k + 1][0]);
                acc1 += __popc((a[r][k + 1][1] ^ w.y) & v[r][k + 1][1]);
                acc1 += __popc((a[r][k + 1][2] ^ w.z) & v[r][k + 1][2]);
                acc1 += __popc((a[r][k + 1][3] ^ w.w) & v[r][k + 1][3]);
            }
        }
        float al = alsm[o];
        float2 res;
        res.x = al * (float)(vsum0 - 2 * acc0);
        res.y = al * (float)(vsum1 - 2 * acc1);
        *(float2*)(outp + (size_t)o * (HW * HW)) = res;
    }
}

// ============================================================
extern "C" void kernel_launch(void* const* d_in, const int* in_sizes, int n_in,
                              void* d_out, int out_size)
{
    const float* x     = (const float*)d_in[0];  // (32,128,56,56)
    const float* Alpha = (const float*)d_in[1];  // (128,1,1)
    const float* M     = (const float*)d_in[2];  // (128,128,3,3)
    const float* Z     = (const float*)d_in[3];  // (5,128,128,3,3)
    const float* rv    = (const float*)d_in[4];  // (1,5)
    float* out = (float*)d_out;

    // 1) weight synthesis + sign pack: 4608 warps
    k_weights<<<576, 256>>>(M, Z, rv);

    // 2) activation binarize + pack (zero-bordered 58x58)
    k_pack<<<dim3(PHW, NB), 64>>>(x);

    // 3) XNOR-popcount conv + Alpha scale
    k_conv<<<dim3(HW, NB), 224>>>(Alpha, out);
}